// round 1
// baseline (speedup 1.0000x reference)
#include <cuda_runtime.h>

#define N_ROWS  131072
#define C_DIM   256
#define K_CODES 1024
#define NZQ     33554432
#define HWSZ    4096

// scratch (no allocation allowed)
__device__ float g_embT[C_DIM * K_CODES];   // emb transposed [c][k]
__device__ float g_e2[K_CODES];             // ||e_k||^2
__device__ int   g_idx[N_ROWS];             // argmin indices
__device__ float g_partial[1024];           // loss partials

// ---------- packed f32x2 helpers (sm_103a full-rate fp32) ----------
__device__ __forceinline__ unsigned long long pk2(float lo, float hi){
  unsigned long long r; asm("mov.b64 %0, {%1, %2};" : "=l"(r) : "f"(lo), "f"(hi)); return r;
}
__device__ __forceinline__ void unpk2(unsigned long long v, float &lo, float &hi){
  asm("mov.b64 {%0, %1}, %2;" : "=f"(lo), "=f"(hi) : "l"(v));
}
__device__ __forceinline__ unsigned long long fma2(unsigned long long a, unsigned long long b, unsigned long long c){
  unsigned long long d; asm("fma.rn.f32x2 %0, %1, %2, %3;" : "=l"(d) : "l"(a), "l"(b), "l"(c)); return d;
}

// ---------- kernel 1: transpose emb + ||e||^2 ----------
__global__ void prep_emb(const float* __restrict__ emb){
  int k = blockIdx.x, c = threadIdx.x;
  float v = emb[k * C_DIM + c];
  g_embT[c * K_CODES + k] = v;
  __shared__ float red[C_DIM];
  red[c] = __fmul_rn(v, v);
  __syncthreads();
  for (int s = 128; s > 0; s >>= 1){
    if (c < s) red[c] = __fadd_rn(red[c], red[c + s]);
    __syncthreads();
  }
  if (c == 0) g_e2[k] = red[0];
}

// ---------- kernel 2: fused GEMM + argmin ----------
// smem: Zs[256][128] | Es[2][16][128] | z2s[128] | e2s[128]
#define SMEM_FLOATS 37120
#define SMEM_BYTES  (SMEM_FLOATS * 4)

__global__ __launch_bounds__(256, 1) void vq_main(const float* __restrict__ z,
                                                  float* __restrict__ out,
                                                  int out_size){
  extern __shared__ float sm[];
  float* Zs  = sm;            // 32768 floats
  float* Es  = sm + 32768;    // 4096 floats (2 x 16 x 128)
  float* z2s = sm + 36864;    // 128
  float* e2s = sm + 36992;    // 128

  const int t  = threadIdx.x;
  const int tx = t & 15, ty = t >> 4;
  const int n0 = blockIdx.x * 128;
  const int b  = n0 >> 12;
  const int hw0 = n0 & 4095;
  const float* zb = z + (size_t)b * (C_DIM * HWSZ) + hw0;

  // load the whole z row-tile once: [256 c][128 rows], coalesced float4
  #pragma unroll 4
  for (int i = t; i < 8192; i += 256){
    int c = i >> 5, r4 = (i & 31) << 2;
    *(float4*)&Zs[c * 128 + r4] = *(const float4*)&zb[(size_t)c * HWSZ + r4];
  }
  __syncthreads();

  // ||z||^2 per row (sequential over c, square-then-add like the reference)
  if (t < 128){
    float s = 0.f;
    #pragma unroll 8
    for (int c = 0; c < 256; ++c){
      float v = Zs[c * 128 + t];
      s = __fadd_rn(s, __fmul_rn(v, v));
    }
    z2s[t] = s;
  }

  float minv[8]; int mini[8];
  #pragma unroll
  for (int r = 0; r < 8; ++r){ minv[r] = 3.4028235e38f; mini[r] = 0; }

  const unsigned es_base = (unsigned)__cvta_generic_to_shared(Es);
  const int kkld = t >> 4, q = t & 15;   // cp.async mapping: 16 rows x 16 threads

  for (int nt = 0; nt < 8; ++nt){
    if (t < 128) e2s[t] = g_e2[nt * 128 + t];

    unsigned long long acc[8][4];
    #pragma unroll
    for (int r = 0; r < 8; ++r){
      acc[r][0] = 0ull; acc[r][1] = 0ull; acc[r][2] = 0ull; acc[r][3] = 0ull;
    }

    const float* src = g_embT + nt * 128;

    // prologue: chunk 0 -> buf 0
    {
      const float* gp = src + (size_t)kkld * K_CODES + q * 8;
      unsigned sa = es_base + ((kkld * 128 + q * 8) << 2);
      asm volatile("cp.async.cg.shared.global [%0], [%1], 16;" :: "r"(sa), "l"(gp));
      asm volatile("cp.async.cg.shared.global [%0], [%1], 16;" :: "r"(sa + 16), "l"(gp + 4));
      asm volatile("cp.async.commit_group;");
    }

    int buf = 0;
    for (int ch = 0; ch < 16; ++ch){
      if (ch < 15){
        const float* gp = src + (size_t)((ch + 1) * 16 + kkld) * K_CODES + q * 8;
        unsigned sa = es_base + ((((buf ^ 1) * 2048) + kkld * 128 + q * 8) << 2);
        asm volatile("cp.async.cg.shared.global [%0], [%1], 16;" :: "r"(sa), "l"(gp));
        asm volatile("cp.async.cg.shared.global [%0], [%1], 16;" :: "r"(sa + 16), "l"(gp + 4));
        asm volatile("cp.async.commit_group;");
        asm volatile("cp.async.wait_group 1;");
      } else {
        asm volatile("cp.async.wait_group 0;");
      }
      __syncthreads();

      const float* Eb = Es + buf * 2048;
      #pragma unroll
      for (int k2 = 0; k2 < 16; ++k2){
        const int c = ch * 16 + k2;
        float4 a0 = *(const float4*)&Zs[c * 128 + ty * 8];
        float4 a1 = *(const float4*)&Zs[c * 128 + ty * 8 + 4];
        ulonglong2 bv0 = *(const ulonglong2*)&Eb[k2 * 128 + tx * 8];
        ulonglong2 bv1 = *(const ulonglong2*)&Eb[k2 * 128 + tx * 8 + 4];
        const float av[8] = {a0.x, a0.y, a0.z, a0.w, a1.x, a1.y, a1.z, a1.w};
        const unsigned long long bb0 = bv0.x, bb1 = bv0.y, bb2 = bv1.x, bb3 = bv1.y;
        #pragma unroll
        for (int r = 0; r < 8; ++r){
          unsigned long long aa = pk2(av[r], av[r]);
          acc[r][0] = fma2(aa, bb0, acc[r][0]);
          acc[r][1] = fma2(aa, bb1, acc[r][1]);
          acc[r][2] = fma2(aa, bb2, acc[r][2]);
          acc[r][3] = fma2(aa, bb3, acc[r][3]);
        }
      }
      __syncthreads();
      buf ^= 1;
    }

    // per-tile argmin epilogue, replicating reference rounding:
    // d = fl( fl(z2 + e2) - fl(2*dot) ), ties -> lowest k
    #pragma unroll
    for (int r = 0; r < 8; ++r){
      float z2v = z2s[ty * 8 + r];
      float bv = 0.f; int bi = 0;
      #pragma unroll
      for (int j = 0; j < 4; ++j){
        float d0, d1; unpk2(acc[r][j], d0, d1);
        int k0 = nt * 128 + tx * 8 + j * 2;
        float s0 = __fadd_rn(z2v, e2s[tx * 8 + j * 2]);
        float s1 = __fadd_rn(z2v, e2s[tx * 8 + j * 2 + 1]);
        float dist0 = __fsub_rn(s0, __fmul_rn(2.0f, d0));
        float dist1 = __fsub_rn(s1, __fmul_rn(2.0f, d1));
        if (j == 0){ bv = dist0; bi = k0; }
        else if (dist0 < bv){ bv = dist0; bi = k0; }
        if (dist1 < bv){ bv = dist1; bi = k0 + 1; }
      }
      // reduce across the 16 lanes owning this row (xor <= 8 stays in-group)
      #pragma unroll
      for (int m = 8; m >= 1; m >>= 1){
        float ov = __shfl_xor_sync(0xffffffffu, bv, m);
        int   oi = __shfl_xor_sync(0xffffffffu, bi, m);
        if (ov < bv || (ov == bv && oi < bi)){ bv = ov; bi = oi; }
      }
      if (bv < minv[r]){ minv[r] = bv; mini[r] = bi; }  // ascending k => ties keep lower
    }
    __syncthreads();   // protect e2s / Es reuse next nt
  }

  if (tx == 0){
    #pragma unroll
    for (int r = 0; r < 8; ++r){
      int grow = n0 + ty * 8 + r;
      g_idx[grow] = mini[r];
      if (out_size >= NZQ + N_ROWS) out[NZQ + grow] = (float)mini[r];
    }
  }
}

// ---------- kernel 3: gather zq, straight-through output, loss partials ----------
__global__ __launch_bounds__(256, 1) void vq_epi(const float* __restrict__ z,
                                                 const float* __restrict__ emb,
                                                 float* __restrict__ out,
                                                 int out_size){
  __shared__ int sidx[128];
  __shared__ float red[256];
  const int t = threadIdx.x;
  const int n0 = blockIdx.x * 128;
  if (t < 128) sidx[t] = g_idx[n0 + t];
  __syncthreads();
  const int b = n0 >> 12, hw0 = n0 & 4095;
  const size_t base = (size_t)b * (C_DIM * HWSZ) + hw0;
  const int i = t & 127, half = t >> 7;
  const int code = sidx[i];
  const float* erow = emb + (size_t)code * C_DIM;
  float acc = 0.f;
  const bool wr = (out_size >= NZQ);
  #pragma unroll 4
  for (int c = half; c < 256; c += 2){
    float e  = __ldg(&erow[c]);
    size_t a = base + (size_t)c * HWSZ + i;
    float zp = z[a];
    float d  = __fsub_rn(e, zp);           // fl(zq - zp)  (loss term)
    if (wr) out[a] = __fadd_rn(zp, d);     // fl(zp + fl(zq - zp))  (straight-through)
    acc = __fadd_rn(acc, __fmul_rn(d, d));
  }
  red[t] = acc;
  __syncthreads();
  for (int s = 128; s > 0; s >>= 1){
    if (t < s) red[t] = __fadd_rn(red[t], red[t + s]);
    __syncthreads();
  }
  if (t == 0) g_partial[blockIdx.x] = red[0];
}

// ---------- kernel 4: deterministic final loss reduce ----------
__global__ void vq_fin(float* __restrict__ out, int out_size){
  __shared__ double dred[256];
  const int t = threadIdx.x;
  double s = 0.0;
  for (int ii = t; ii < 1024; ii += 256) s += (double)g_partial[ii];
  dred[t] = s;
  __syncthreads();
  for (int k = 128; k > 0; k >>= 1){
    if (t < k) dred[t] += dred[t + k];
    __syncthreads();
  }
  if (t == 0 && out_size >= NZQ + N_ROWS + 1){
    float m1 = (float)(dred[0] / 33554432.0);              // n = 2^25, exact divide
    float loss = __fsub_rn(m1, __fmul_rn(0.25f, m1));      // m1 - beta*m2 (m2 == m1)
    out[NZQ + N_ROWS] = loss;
  }
}

extern "C" void kernel_launch(void* const* d_in, const int* in_sizes, int n_in,
                              void* d_out, int out_size){
  const float* z   = (const float*)d_in[0];
  const float* emb = (const float*)d_in[1];
  float* out = (float*)d_out;
  (void)in_sizes; (void)n_in;

  cudaFuncSetAttribute(vq_main, cudaFuncAttributeMaxDynamicSharedMemorySize, SMEM_BYTES);

  prep_emb<<<K_CODES, C_DIM>>>(emb);
  vq_main<<<N_ROWS / 128, 256, SMEM_BYTES>>>(z, out, out_size);
  vq_epi<<<N_ROWS / 128, 256>>>(z, emb, out, out_size);
  vq_fin<<<1, 256>>>(out, out_size);
}

// round 3
// speedup vs baseline: 1.3758x; 1.3758x over previous
#include <cuda_runtime.h>
#include <cuda_bf16.h>
#include <cstdint>

#define N_ROWS  131072
#define C_DIM   256
#define K_CODES 1024
#define NZQ     33554432
#define HWSZ    4096

// ---- device scratch (statics; no runtime allocation) ----
__device__ __nv_bfloat16 g_zs[3u * N_ROWS * C_DIM];   // z splits, row-major [s][n][c]  (201MB)
__device__ __nv_bfloat16 g_es[3u * K_CODES * C_DIM];  // emb splits [s][k][c]           (1.5MB)
__device__ float g_z2[N_ROWS];
__device__ float g_e2[K_CODES];
__device__ int   g_idx[N_ROWS];
__device__ float g_partial[1024];

__device__ __forceinline__ uint32_t smem_u32(const void* p){
  uint32_t a;
  asm("{ .reg .u64 t; cvta.to.shared.u64 t, %1; cvt.u32.u64 %0, t; }" : "=r"(a) : "l"(p));
  return a;
}
__device__ __forceinline__ uint32_t swz(uint32_t off){ return off ^ ((off >> 3) & 0x70); }

__device__ __forceinline__ void split3(float v, uint32_t &s0, uint32_t &s1, uint32_t &s2){
  __nv_bfloat16 b0 = __float2bfloat16(v);
  float r1 = __fsub_rn(v, __bfloat162float(b0));
  __nv_bfloat16 b1 = __float2bfloat16(r1);
  float r2 = __fsub_rn(r1, __bfloat162float(b1));
  __nv_bfloat16 b2 = __float2bfloat16(r2);
  s0 = (uint32_t)__bfloat16_as_ushort(b0);
  s1 = (uint32_t)__bfloat16_as_ushort(b1);
  s2 = (uint32_t)__bfloat16_as_ushort(b2);
}

#define CPASYNC16(dst, src) \
  asm volatile("cp.async.cg.shared.global [%0], [%1], 16;" :: "r"(dst), "l"(src))
#define CPCOMMIT() asm volatile("cp.async.commit_group;")

#define LDSM_X4(r0,r1,r2,r3,addr) \
  asm volatile("ldmatrix.sync.aligned.m8n8.x4.shared.b16 {%0,%1,%2,%3}, [%4];" \
    : "=r"(r0), "=r"(r1), "=r"(r2), "=r"(r3) : "r"(addr))

#define MMA16816(c0,c1,c2,c3,a0,a1,a2,a3,b0,b1) \
  asm volatile("mma.sync.aligned.m16n8k16.row.col.f32.bf16.bf16.f32 " \
    "{%0,%1,%2,%3}, {%4,%5,%6,%7}, {%8,%9}, {%0,%1,%2,%3};" \
    : "+f"(c0), "+f"(c1), "+f"(c2), "+f"(c3) \
    : "r"(a0), "r"(a1), "r"(a2), "r"(a3), "r"(b0), "r"(b1))

// ---------------- prep: emb splits + ||e||^2 ----------------
__global__ void prep_e(const float* __restrict__ emb){
  int k = blockIdx.x, c = threadIdx.x;
  float v = emb[k * C_DIM + c];
  uint32_t s0, s1, s2;
  split3(v, s0, s1, s2);
  g_es[(0u * K_CODES + k) * C_DIM + c] = __ushort_as_bfloat16((unsigned short)s0);
  g_es[(1u * K_CODES + k) * C_DIM + c] = __ushort_as_bfloat16((unsigned short)s1);
  g_es[(2u * K_CODES + k) * C_DIM + c] = __ushort_as_bfloat16((unsigned short)s2);
  __shared__ float red[C_DIM];
  red[c] = __fmul_rn(v, v);
  __syncthreads();
  for (int s = 128; s > 0; s >>= 1){
    if (c < s) red[c] = __fadd_rn(red[c], red[c + s]);
    __syncthreads();
  }
  if (c == 0) g_e2[k] = red[0];
}

// ---------------- prep: z transpose + split ----------------
// z[b][c][hw] -> g_zs[s][n = b*4096+hw][c]
__global__ __launch_bounds__(256) void prep_z(const float* __restrict__ z){
  __shared__ float tile[32][33];
  const int t = threadIdx.x;
  const int hw0 = blockIdx.x * 32, c0 = blockIdx.y * 32, b = blockIdx.z;
  const int hh = t & 31, cbase = t >> 5;
  #pragma unroll
  for (int q = 0; q < 4; ++q){
    int cc = cbase + q * 8;
    tile[cc][hh] = z[((size_t)(b * 256 + c0 + cc)) * HWSZ + hw0 + hh];
  }
  __syncthreads();
  const int nn = t >> 3, c4 = (t & 7) * 4;
  const size_t n = (size_t)b * HWSZ + hw0 + nn;
  uint32_t u[3][4];
  #pragma unroll
  for (int q = 0; q < 4; ++q){
    uint32_t s0, s1, s2;
    split3(tile[c4 + q][nn], s0, s1, s2);
    u[0][q] = s0; u[1][q] = s1; u[2][q] = s2;
  }
  #pragma unroll
  for (int s = 0; s < 3; ++s){
    uint32_t* dst = (uint32_t*)&g_zs[((size_t)s * N_ROWS + n) * C_DIM + c0 + c4];
    dst[0] = u[s][0] | (u[s][1] << 16);
    dst[1] = u[s][2] | (u[s][3] << 16);
  }
}

// ---------------- prep: ||z||^2 (sequential ascending c, matches R1 exactly) ----------------
__global__ __launch_bounds__(256) void prep_z2(const float* __restrict__ z){
  const int n = blockIdx.x * 256 + threadIdx.x;
  const int b = n >> 12, hw = n & 4095;
  const float* p = z + (size_t)b * (C_DIM * HWSZ) + hw;
  float acc = 0.f;
  #pragma unroll 8
  for (int c = 0; c < 256; ++c){
    float v = p[(size_t)c * HWSZ];
    acc = __fadd_rn(acc, __fmul_rn(v, v));
  }
  g_z2[n] = acc;
}

// ---------------- main: bf16-split HMMA GEMM + argmin ----------------
// smem: [buf0: A 48K | B 48K][buf1: A | B] | e2s 4K | sminv 512 | smini 512
#define STG_A(buf) ((buf) * 98304)
#define STG_B(buf) ((buf) * 98304 + 49152)
#define OFF_E2S    196608
#define OFF_SMINV  200704
#define OFF_SMINI  201216
#define SM_TOTAL   201728

__global__ __launch_bounds__(256, 1) void vq_main(float* __restrict__ out, int out_size){
  extern __shared__ char smem[];
  const uint32_t sb = smem_u32(smem);
  float* e2s  = (float*)(smem + OFF_E2S);
  float* sminv = (float*)(smem + OFF_SMINV);
  int*   smini = (int*)(smem + OFF_SMINI);

  const int t = threadIdx.x, w = t >> 5, l = t & 31;
  const int wm = (w & 3) * 32;        // row offset of warp tile
  const int wn = (w >> 2) * 64;       // code offset of warp tile within 128-tile
  const int n0 = blockIdx.x * 128;

  // ---- cp.async issue for one (nt,kc) stage ----
  auto issue = [&](int stage){
    const int nt2 = stage >> 2, kc2 = stage & 3, buf = stage & 1;
    #pragma unroll
    for (int i = 0; i < 12; ++i){
      int id = t + i * 256;
      int s = id >> 10, rem = id & 1023, r = rem >> 3, j = rem & 7;
      const __nv_bfloat16* src = g_zs + ((size_t)s * N_ROWS + n0 + r) * C_DIM + kc2 * 64 + j * 8;
      CPASYNC16(sb + STG_A(buf) + s * 16384 + swz((uint32_t)(r * 128 + j * 16)), src);
    }
    #pragma unroll
    for (int i = 0; i < 12; ++i){
      int id = t + i * 256;
      int s = id >> 10, rem = id & 1023, r = rem >> 3, j = rem & 7;
      const __nv_bfloat16* src = g_es + ((size_t)s * K_CODES + nt2 * 128 + r) * C_DIM + kc2 * 64 + j * 8;
      CPASYNC16(sb + STG_B(buf) + s * 16384 + swz((uint32_t)(r * 128 + j * 16)), src);
    }
    CPCOMMIT();
  };

  issue(0);
  issue(1);

  // stage e2 + z2 while cp.async runs
  for (int i = t; i < 1024; i += 256) e2s[i] = g_e2[i];
  float z2r[4];
  #pragma unroll
  for (int slot = 0; slot < 4; ++slot){
    int row = wm + (slot >> 1) * 16 + (l >> 2) + (slot & 1) * 8;
    z2r[slot] = g_z2[n0 + row];
  }
  __syncthreads();

  float acc[2][8][4];
  float minv[4]; int mini[4];
  #pragma unroll
  for (int s2 = 0; s2 < 4; ++s2){ minv[s2] = 3.4028235e38f; mini[s2] = 0; }

  const int pa[6] = {0,0,1,0,1,2}, pb[6] = {0,1,0,2,1,0};

  for (int st = 0; st < 32; ++st){
    const int nt = st >> 2, kc = st & 3, buf = st & 1;

    if (st < 31) asm volatile("cp.async.wait_group 1;" ::: "memory");
    else         asm volatile("cp.async.wait_group 0;" ::: "memory");
    __syncthreads();

    if (kc == 0){
      #pragma unroll
      for (int ma = 0; ma < 2; ++ma)
        #pragma unroll
        for (int na = 0; na < 8; ++na)
          #pragma unroll
          for (int q = 0; q < 4; ++q) acc[ma][na][q] = 0.f;
    }

    const uint32_t Ab = sb + STG_A(buf), Bb = sb + STG_B(buf);
    #pragma unroll
    for (int k16 = 0; k16 < 4; ++k16){
      const uint32_t kbyte = (uint32_t)(k16 * 32);
      uint32_t af[3][2][4], bf[3][8][2];
      #pragma unroll
      for (int s = 0; s < 3; ++s){
        #pragma unroll
        for (int ma = 0; ma < 2; ++ma){
          uint32_t row = (uint32_t)(wm + ma * 16 + (l & 7) + ((l >> 3) & 1) * 8);
          uint32_t ad = Ab + s * 16384 + swz(row * 128 + kbyte + ((l >> 4) << 4));
          LDSM_X4(af[s][ma][0], af[s][ma][1], af[s][ma][2], af[s][ma][3], ad);
        }
        #pragma unroll
        for (int p = 0; p < 4; ++p){
          uint32_t nrow = (uint32_t)(wn + p * 16 + ((l >> 4) << 3) + (l & 7));
          uint32_t bd = Bb + s * 16384 + swz(nrow * 128 + kbyte + (((l >> 3) & 1) << 4));
          LDSM_X4(bf[s][2*p][0], bf[s][2*p][1], bf[s][2*p+1][0], bf[s][2*p+1][1], bd);
        }
      }
      #pragma unroll
      for (int p = 0; p < 6; ++p){
        const int sa = pa[p], sbp = pb[p];
        #pragma unroll
        for (int ma = 0; ma < 2; ++ma)
          #pragma unroll
          for (int na = 0; na < 8; ++na)
            MMA16816(acc[ma][na][0], acc[ma][na][1], acc[ma][na][2], acc[ma][na][3],
                     af[sa][ma][0], af[sa][ma][1], af[sa][ma][2], af[sa][ma][3],
                     bf[sbp][na][0], bf[sbp][na][1]);
      }
    }
    __syncthreads();
    if (st + 2 < 32) issue(st + 2);

    // ---- per-nt argmin epilogue (registers + e2s only) ----
    if (kc == 3){
      #pragma unroll
      for (int na = 0; na < 8; ++na){
        #pragma unroll
        for (int c2 = 0; c2 < 2; ++c2){
          int code = nt * 128 + wn + na * 8 + (l & 3) * 2 + c2;
          float e2v = e2s[code];
          #pragma unroll
          for (int ma = 0; ma < 2; ++ma){
            #pragma unroll
            for (int h = 0; h < 2; ++h){
              int slot = ma * 2 + h;
              float dot = acc[ma][na][h * 2 + c2];
              float sd = __fadd_rn(z2r[slot], e2v);
              float dist = __fsub_rn(sd, __fmul_rn(2.0f, dot));
              if (dist < minv[slot]){ minv[slot] = dist; mini[slot] = code; }
            }
          }
        }
      }
    }
  }

  // reduce across the 4 lanes sharing each row (lane-group l&3)
  #pragma unroll
  for (int slot = 0; slot < 4; ++slot){
    #pragma unroll
    for (int m = 1; m <= 2; m <<= 1){
      float ov = __shfl_xor_sync(0xffffffffu, minv[slot], m);
      int   oi = __shfl_xor_sync(0xffffffffu, mini[slot], m);
      if (ov < minv[slot] || (ov == minv[slot] && oi < mini[slot])){ minv[slot] = ov; mini[slot] = oi; }
    }
  }
  // cross-warp (wn halves) combine via smem
  if (w >= 4 && (l & 3) == 0){
    #pragma unroll
    for (int slot = 0; slot < 4; ++slot){
      int row = wm + (slot >> 1) * 16 + (l >> 2) + (slot & 1) * 8;
      sminv[row] = minv[slot]; smini[row] = mini[slot];
    }
  }
  __syncthreads();
  if (w < 4 && (l & 3) == 0){
    #pragma unroll
    for (int slot = 0; slot < 4; ++slot){
      int row = wm + (slot >> 1) * 16 + (l >> 2) + (slot & 1) * 8;
      float ov = sminv[row]; int oi = smini[row];
      float bv = minv[slot]; int bi = mini[slot];
      if (ov < bv || (ov == bv && oi < bi)){ bv = ov; bi = oi; }
      int grow = n0 + row;
      g_idx[grow] = bi;
      if (out_size >= NZQ + N_ROWS) out[NZQ + grow] = (float)bi;
    }
  }
}

// ---------------- epilogue: gather zq, straight-through, loss partials ----------------
__global__ __launch_bounds__(256, 1) void vq_epi(const float* __restrict__ z,
                                                 const float* __restrict__ emb,
                                                 float* __restrict__ out,
                                                 int out_size){
  __shared__ int sidx[128];
  __shared__ float red[256];
  const int t = threadIdx.x;
  const int n0 = blockIdx.x * 128;
  if (t < 128) sidx[t] = g_idx[n0 + t];
  __syncthreads();
  const int b = n0 >> 12, hw0 = n0 & 4095;
  const size_t base = (size_t)b * (C_DIM * HWSZ) + hw0;
  const int i = t & 127, half = t >> 7;
  const int code = sidx[i];
  const float* erow = emb + (size_t)code * C_DIM;
  float acc = 0.f;
  const bool wr = (out_size >= NZQ);
  #pragma unroll 4
  for (int c = half; c < 256; c += 2){
    float e  = __ldg(&erow[c]);
    size_t a = base + (size_t)c * HWSZ + i;
    float zp = z[a];
    float d  = __fsub_rn(e, zp);
    if (wr) out[a] = __fadd_rn(zp, d);
    acc = __fadd_rn(acc, __fmul_rn(d, d));
  }
  red[t] = acc;
  __syncthreads();
  for (int s = 128; s > 0; s >>= 1){
    if (t < s) red[t] = __fadd_rn(red[t], red[t + s]);
    __syncthreads();
  }
  if (t == 0) g_partial[blockIdx.x] = red[0];
}

__global__ void vq_fin(float* __restrict__ out, int out_size){
  __shared__ double dred[256];
  const int t = threadIdx.x;
  double s = 0.0;
  for (int ii = t; ii < 1024; ii += 256) s += (double)g_partial[ii];
  dred[t] = s;
  __syncthreads();
  for (int k = 128; k > 0; k >>= 1){
    if (t < k) dred[t] += dred[t + k];
    __syncthreads();
  }
  if (t == 0 && out_size >= NZQ + N_ROWS + 1){
    float m1 = (float)(dred[0] / 33554432.0);
    float loss = __fsub_rn(m1, __fmul_rn(0.25f, m1));
    out[NZQ + N_ROWS] = loss;
  }
}

extern "C" void kernel_launch(void* const* d_in, const int* in_sizes, int n_in,
                              void* d_out, int out_size){
  const float* z   = (const float*)d_in[0];
  const float* emb = (const float*)d_in[1];
  float* out = (float*)d_out;
  (void)in_sizes; (void)n_in;

  cudaFuncSetAttribute(vq_main, cudaFuncAttributeMaxDynamicSharedMemorySize, SM_TOTAL);

  prep_e<<<K_CODES, C_DIM>>>(emb);
  prep_z<<<dim3(128, 8, 32), 256>>>(z);
  prep_z2<<<N_ROWS / 256, 256>>>(z);
  vq_main<<<N_ROWS / 128, 256, SM_TOTAL>>>(out, out_size);
  vq_epi<<<N_ROWS / 128, 256>>>(z, emb, out, out_size);
  vq_fin<<<1, 256>>>(out, out_size);
}

// round 5
// speedup vs baseline: 2.1162x; 1.5382x over previous
#include <cuda_runtime.h>
#include <cuda_fp16.h>
#include <cstdint>

#define N_ROWS  131072
#define C_DIM   256
#define K_CODES 1024
#define NZQ     33554432
#define HWSZ    4096

#define ESCALE    4096.0f          // 2^12: lift emb splits out of fp16 subnormal range
#define EINVSCALE 0.000244140625f  // 2^-12 (exact)

// ---- device scratch ----
__device__ __half g_es[2u * K_CODES * C_DIM];   // emb fp16 2-splits of (e * 2^12)
__device__ float  g_e2[K_CODES];
__device__ float  g_partial[1024];

__device__ __forceinline__ uint32_t smem_u32(const void* p){
  uint32_t a;
  asm("{ .reg .u64 t; cvta.to.shared.u64 t, %1; cvt.u32.u64 %0, t; }" : "=r"(a) : "l"(p));
  return a;
}
__device__ __forceinline__ uint32_t swz(uint32_t off){ return off ^ ((off >> 3) & 0x70); }

__device__ __forceinline__ void split2(float v, uint32_t &s0, uint32_t &s1){
  __half h0 = __float2half_rn(v);
  float r  = __fsub_rn(v, __half2float(h0));
  __half h1 = __float2half_rn(r);
  s0 = (uint32_t)__half_as_ushort(h0);
  s1 = (uint32_t)__half_as_ushort(h1);
}

#define CPASYNC16(dst, src) \
  asm volatile("cp.async.cg.shared.global [%0], [%1], 16;" :: "r"(dst), "l"(src))
#define CPCOMMIT() asm volatile("cp.async.commit_group;")

#define LDSM_X4(r0,r1,r2,r3,addr) \
  asm volatile("ldmatrix.sync.aligned.m8n8.x4.shared.b16 {%0,%1,%2,%3}, [%4];" \
    : "=r"(r0), "=r"(r1), "=r"(r2), "=r"(r3) : "r"(addr))

#define MMA16816(c0,c1,c2,c3,a0,a1,a2,a3,b0,b1) \
  asm volatile("mma.sync.aligned.m16n8k16.row.col.f32.f16.f16.f32 " \
    "{%0,%1,%2,%3}, {%4,%5,%6,%7}, {%8,%9}, {%0,%1,%2,%3};" \
    : "+f"(c0), "+f"(c1), "+f"(c2), "+f"(c3) \
    : "r"(a0), "r"(a1), "r"(a2), "r"(a3), "r"(b0), "r"(b1))

#define STS128(addr, a0, a1, a2, a3) \
  asm volatile("st.shared.v4.b32 [%0], {%1,%2,%3,%4};" :: "r"(addr), "r"(a0), "r"(a1), "r"(a2), "r"(a3) : "memory")

// ---------------- prep: emb fp16 splits (scaled by 2^12) + ||e||^2 (unscaled) ----------------
__global__ void prep_e(const float* __restrict__ emb){
  int k = blockIdx.x, c = threadIdx.x;
  float v = emb[k * C_DIM + c];
  uint32_t s0, s1;
  split2(v * ESCALE, s0, s1);   // exact scaling by power of two
  g_es[(0u * K_CODES + k) * C_DIM + c] = __ushort_as_half((unsigned short)s0);
  g_es[(1u * K_CODES + k) * C_DIM + c] = __ushort_as_half((unsigned short)s1);
  __shared__ float red[C_DIM];
  red[c] = __fmul_rn(v, v);
  __syncthreads();
  for (int s = 128; s > 0; s >>= 1){
    if (c < s) red[c] = __fadd_rn(red[c], red[c + s]);
    __syncthreads();
  }
  if (c == 0) g_e2[k] = red[0];
}

// ---------------- main: fused split + HMMA GEMM + argmin + epilogue ----------------
// smem: A[4 kc][2 s][128 row][64 c]fp16 =128K | B[2 buf][2 s][128][64] =64K | e2s 4K | z2s | sminv | smini | sidx | red
#define SM_A      0
#define SM_B      131072
#define OFF_E2S   196608
#define OFF_Z2S   200704
#define OFF_SMINV 201216
#define OFF_SMINI 201728
#define OFF_SIDX  202240
#define OFF_RED   202752
#define SM_TOTAL  203776

__global__ __launch_bounds__(256, 1) void vq_main(const float* __restrict__ z,
                                                  const float* __restrict__ emb,
                                                  float* __restrict__ out,
                                                  int out_size){
  extern __shared__ char smem[];
  const uint32_t sb = smem_u32(smem);
  float* e2s   = (float*)(smem + OFF_E2S);
  float* z2s   = (float*)(smem + OFF_Z2S);
  float* sminv = (float*)(smem + OFF_SMINV);
  int*   smini = (int*)(smem + OFF_SMINI);
  int*   sidx  = (int*)(smem + OFF_SIDX);
  float* red   = (float*)(smem + OFF_RED);

  const int t = threadIdx.x, w = t >> 5, l = t & 31;
  const int wm = (w & 3) * 32;
  const int wn = (w >> 2) * 64;
  const int n0 = blockIdx.x * 128;
  const int b  = n0 >> 12, hw0 = n0 & 4095;
  const float* zb = z + (size_t)b * (C_DIM * HWSZ) + hw0;

  // ---- B cp.async issue for one (nt,kc) stage: 32KB ----
  auto issue = [&](int stage){
    const int nt2 = stage >> 2, kc2 = stage & 3, buf = stage & 1;
    #pragma unroll
    for (int i = 0; i < 8; ++i){
      int id = t + i * 256;
      int s = id >> 10, rem = id & 1023, r = rem >> 3, j = rem & 7;
      const __half* src = g_es + ((size_t)s * K_CODES + nt2 * 128 + r) * C_DIM + kc2 * 64 + j * 8;
      CPASYNC16(sb + SM_B + buf * 32768 + s * 16384 + swz((uint32_t)(r * 128 + j * 16)), src);
    }
    CPCOMMIT();
  };

  issue(0);
  issue(1);

  // ---- phase 1: load z tile, z^2 (ascending c, exact), fp16 split -> A smem ----
  if (t < 128){
    float acc = 0.f;
    #pragma unroll 4
    for (int cg = 0; cg < 32; ++cg){
      uint32_t p0[4], p1[4];
      #pragma unroll
      for (int j2 = 0; j2 < 4; ++j2){
        int c = cg * 8 + j2 * 2;
        float va = __ldg(zb + (size_t)c * HWSZ + t);
        float vb = __ldg(zb + (size_t)(c + 1) * HWSZ + t);
        acc = __fadd_rn(acc, __fmul_rn(va, va));
        acc = __fadd_rn(acc, __fmul_rn(vb, vb));
        uint32_t a0, a1, b0, b1;
        split2(va, a0, a1); split2(vb, b0, b1);
        p0[j2] = a0 | (b0 << 16);
        p1[j2] = a1 | (b1 << 16);
      }
      uint32_t base = sb + SM_A + (uint32_t)(cg >> 3) * 32768;
      uint32_t ad = swz((uint32_t)(t * 128 + (cg & 7) * 16));
      STS128(base + ad,          p0[0], p0[1], p0[2], p0[3]);
      STS128(base + 16384 + ad,  p1[0], p1[1], p1[2], p1[3]);
    }
    z2s[t] = acc;
  } else {
    for (int i = t - 128; i < 1024; i += 128) e2s[i] = g_e2[i];
  }
  __syncthreads();

  float z2r[4];
  #pragma unroll
  for (int slot = 0; slot < 4; ++slot){
    int row = wm + (slot >> 1) * 16 + (l >> 2) + (slot & 1) * 8;
    z2r[slot] = z2s[row];
  }

  float acc[2][8][4];
  float minv[4]; int mini[4];
  #pragma unroll
  for (int s2 = 0; s2 < 4; ++s2){ minv[s2] = 3.4028235e38f; mini[s2] = 0; }

  const int pa[3] = {0,0,1}, pb[3] = {0,1,0};

  for (int st = 0; st < 32; ++st){
    const int nt = st >> 2, kc = st & 3, buf = st & 1;

    if (st < 31) asm volatile("cp.async.wait_group 1;" ::: "memory");
    else         asm volatile("cp.async.wait_group 0;" ::: "memory");
    __syncthreads();

    if (kc == 0){
      #pragma unroll
      for (int ma = 0; ma < 2; ++ma)
        #pragma unroll
        for (int na = 0; na < 8; ++na)
          #pragma unroll
          for (int q = 0; q < 4; ++q) acc[ma][na][q] = 0.f;
    }

    const uint32_t Ab = sb + SM_A + (uint32_t)kc * 32768;
    const uint32_t Bb = sb + SM_B + (uint32_t)buf * 32768;
    #pragma unroll
    for (int k16 = 0; k16 < 4; ++k16){
      const uint32_t kbyte = (uint32_t)(k16 * 32);
      uint32_t af[2][2][4], bf[2][8][2];
      #pragma unroll
      for (int s = 0; s < 2; ++s){
        #pragma unroll
        for (int ma = 0; ma < 2; ++ma){
          uint32_t row = (uint32_t)(wm + ma * 16 + (l & 7) + ((l >> 3) & 1) * 8);
          uint32_t ad = Ab + s * 16384 + swz(row * 128 + kbyte + ((l >> 4) << 4));
          LDSM_X4(af[s][ma][0], af[s][ma][1], af[s][ma][2], af[s][ma][3], ad);
        }
        #pragma unroll
        for (int p = 0; p < 4; ++p){
          uint32_t nrow = (uint32_t)(wn + p * 16 + ((l >> 4) << 3) + (l & 7));
          uint32_t bd = Bb + s * 16384 + swz(nrow * 128 + kbyte + (((l >> 3) & 1) << 4));
          LDSM_X4(bf[s][2*p][0], bf[s][2*p][1], bf[s][2*p+1][0], bf[s][2*p+1][1], bd);
        }
      }
      #pragma unroll
      for (int p = 0; p < 3; ++p){
        const int sa = pa[p], sbp = pb[p];
        #pragma unroll
        for (int ma = 0; ma < 2; ++ma)
          #pragma unroll
          for (int na = 0; na < 8; ++na)
            MMA16816(acc[ma][na][0], acc[ma][na][1], acc[ma][na][2], acc[ma][na][3],
                     af[sa][ma][0], af[sa][ma][1], af[sa][ma][2], af[sa][ma][3],
                     bf[sbp][na][0], bf[sbp][na][1]);
      }
    }
    __syncthreads();
    if (st + 2 < 32) issue(st + 2);

    if (kc == 3){
      #pragma unroll
      for (int na = 0; na < 8; ++na){
        #pragma unroll
        for (int c2 = 0; c2 < 2; ++c2){
          int code = nt * 128 + wn + na * 8 + (l & 3) * 2 + c2;
          float e2v = e2s[code];
          #pragma unroll
          for (int ma = 0; ma < 2; ++ma){
            #pragma unroll
            for (int h = 0; h < 2; ++h){
              int slot = ma * 2 + h;
              float dot = acc[ma][na][h * 2 + c2] * EINVSCALE;  // exact 2^-12 rescale
              float sd = __fadd_rn(z2r[slot], e2v);
              float dist = __fsub_rn(sd, __fmul_rn(2.0f, dot));
              if (dist < minv[slot]){ minv[slot] = dist; mini[slot] = code; }
            }
          }
        }
      }
    }
  }

  // ---- argmin reduce: 4 lanes per row, then cross-warp halves ----
  #pragma unroll
  for (int slot = 0; slot < 4; ++slot){
    #pragma unroll
    for (int m = 1; m <= 2; m <<= 1){
      float ov = __shfl_xor_sync(0xffffffffu, minv[slot], m);
      int   oi = __shfl_xor_sync(0xffffffffu, mini[slot], m);
      if (ov < minv[slot] || (ov == minv[slot] && oi < mini[slot])){ minv[slot] = ov; mini[slot] = oi; }
    }
  }
  if (w >= 4 && (l & 3) == 0){
    #pragma unroll
    for (int slot = 0; slot < 4; ++slot){
      int row = wm + (slot >> 1) * 16 + (l >> 2) + (slot & 1) * 8;
      sminv[row] = minv[slot]; smini[row] = mini[slot];
    }
  }
  __syncthreads();
  if (w < 4 && (l & 3) == 0){
    #pragma unroll
    for (int slot = 0; slot < 4; ++slot){
      int row = wm + (slot >> 1) * 16 + (l >> 2) + (slot & 1) * 8;
      float ov = sminv[row]; int oi = smini[row];
      float bv = minv[slot]; int bi = mini[slot];
      if (ov < bv || (ov == bv && oi < bi)){ bv = ov; bi = oi; }
      sidx[row] = bi;
      if (out_size >= NZQ + N_ROWS) out[NZQ + n0 + row] = (float)bi;
    }
  }
  __syncthreads();

  // ---- fused epilogue: gather zq, straight-through output, loss partial ----
  {
    const int i = t & 127, half = t >> 7;
    const int code = sidx[i];
    const float* erow = emb + (size_t)code * C_DIM;
    float lacc = 0.f;
    const bool wr = (out_size >= NZQ);
    #pragma unroll 4
    for (int c = half; c < 256; c += 2){
      float e  = __ldg(&erow[c]);
      size_t a = (size_t)b * (C_DIM * HWSZ) + hw0 + (size_t)c * HWSZ + i;
      float zp = z[a];
      float d  = __fsub_rn(e, zp);
      if (wr) out[a] = __fadd_rn(zp, d);
      lacc = __fadd_rn(lacc, __fmul_rn(d, d));
    }
    red[t] = lacc;
    __syncthreads();
    for (int s = 128; s > 0; s >>= 1){
      if (t < s) red[t] = __fadd_rn(red[t], red[t + s]);
      __syncthreads();
    }
    if (t == 0) g_partial[blockIdx.x] = red[0];
  }
}

// ---------------- final loss ----------------
__global__ void vq_fin(float* __restrict__ out, int out_size){
  __shared__ double dred[256];
  const int t = threadIdx.x;
  double s = 0.0;
  for (int ii = t; ii < 1024; ii += 256) s += (double)g_partial[ii];
  dred[t] = s;
  __syncthreads();
  for (int k = 128; k > 0; k >>= 1){
    if (t < k) dred[t] += dred[t + k];
    __syncthreads();
  }
  if (t == 0 && out_size >= NZQ + N_ROWS + 1){
    float m1 = (float)(dred[0] / 33554432.0);
    float loss = __fsub_rn(m1, __fmul_rn(0.25f, m1));
    out[NZQ + N_ROWS] = loss;
  }
}

extern "C" void kernel_launch(void* const* d_in, const int* in_sizes, int n_in,
                              void* d_out, int out_size){
  const float* z   = (const float*)d_in[0];
  const float* emb = (const float*)d_in[1];
  float* out = (float*)d_out;
  (void)in_sizes; (void)n_in;

  cudaFuncSetAttribute(vq_main, cudaFuncAttributeMaxDynamicSharedMemorySize, SM_TOTAL);

  prep_e<<<K_CODES, C_DIM>>>(emb);
  vq_main<<<N_ROWS / 128, 256, SM_TOTAL>>>(z, emb, out, out_size);
  vq_fin<<<1, 256>>>(out, out_size);
}

// round 6
// speedup vs baseline: 2.3237x; 1.0980x over previous
#include <cuda_runtime.h>
#include <cuda_fp16.h>
#include <cstdint>

#define N_ROWS  131072
#define C_DIM   256
#define K_CODES 1024
#define NZQ     33554432
#define HWSZ    4096
#define ROWS_CTA 64
#define GRID    (N_ROWS / ROWS_CTA)

#define ESCALE    4096.0f          // 2^12: lift emb splits out of fp16 subnormal range
#define EINVSCALE 0.000244140625f  // 2^-12 (exact)

// ---- device scratch ----
__device__ __half g_es[2u * K_CODES * C_DIM];   // emb fp16 2-splits of (e * 2^12)
__device__ float  g_e2[K_CODES];
__device__ float  g_partial[GRID];

__device__ __forceinline__ uint32_t smem_u32(const void* p){
  uint32_t a;
  asm("{ .reg .u64 t; cvta.to.shared.u64 t, %1; cvt.u32.u64 %0, t; }" : "=r"(a) : "l"(p));
  return a;
}
__device__ __forceinline__ uint32_t swz(uint32_t off){ return off ^ ((off >> 3) & 0x70); }

__device__ __forceinline__ void split2(float v, uint32_t &s0, uint32_t &s1){
  __half h0 = __float2half_rn(v);
  float r  = __fsub_rn(v, __half2float(h0));
  __half h1 = __float2half_rn(r);
  s0 = (uint32_t)__half_as_ushort(h0);
  s1 = (uint32_t)__half_as_ushort(h1);
}

#define CPASYNC16(dst, src) \
  asm volatile("cp.async.cg.shared.global [%0], [%1], 16;" :: "r"(dst), "l"(src))
#define CPCOMMIT() asm volatile("cp.async.commit_group;")

#define LDSM_X4(r0,r1,r2,r3,addr) \
  asm volatile("ldmatrix.sync.aligned.m8n8.x4.shared.b16 {%0,%1,%2,%3}, [%4];" \
    : "=r"(r0), "=r"(r1), "=r"(r2), "=r"(r3) : "r"(addr))

#define MMA16816(c0,c1,c2,c3,a0,a1,a2,a3,b0,b1) \
  asm volatile("mma.sync.aligned.m16n8k16.row.col.f32.f16.f16.f32 " \
    "{%0,%1,%2,%3}, {%4,%5,%6,%7}, {%8,%9}, {%0,%1,%2,%3};" \
    : "+f"(c0), "+f"(c1), "+f"(c2), "+f"(c3) \
    : "r"(a0), "r"(a1), "r"(a2), "r"(a3), "r"(b0), "r"(b1))

#define STS128(addr, a0, a1, a2, a3) \
  asm volatile("st.shared.v4.b32 [%0], {%1,%2,%3,%4};" :: "r"(addr), "r"(a0), "r"(a1), "r"(a2), "r"(a3) : "memory")

// ---------------- prep: emb fp16 splits (scaled by 2^12) + ||e||^2 (unscaled) ----------------
__global__ void prep_e(const float* __restrict__ emb){
  int k = blockIdx.x, c = threadIdx.x;
  float v = emb[k * C_DIM + c];
  uint32_t s0, s1;
  split2(v * ESCALE, s0, s1);
  g_es[(0u * K_CODES + k) * C_DIM + c] = __ushort_as_half((unsigned short)s0);
  g_es[(1u * K_CODES + k) * C_DIM + c] = __ushort_as_half((unsigned short)s1);
  __shared__ float red[C_DIM];
  red[c] = __fmul_rn(v, v);
  __syncthreads();
  for (int s = 128; s > 0; s >>= 1){
    if (c < s) red[c] = __fadd_rn(red[c], red[c + s]);
    __syncthreads();
  }
  if (c == 0) g_e2[k] = red[0];
}

// ---------------- main: fused split + HMMA GEMM + argmin + epilogue (2 CTAs/SM) ----------------
// smem per CTA:
//  A[4 kc][2 s][64 row][64 c] fp16  = 65536
//  B[2 buf][2 s][128 code][32 c]    = 32768   (64B rows, SW128 xor)
//  e2s 4096 | z2s 256 | sminv 1024 | smini 1024 | sidx 256 | red 1024
#define SM_A      0
#define SM_B      65536
#define OFF_E2S   98304
#define OFF_Z2S   102400
#define OFF_SMINV 102656
#define OFF_SMINI 103680
#define OFF_SIDX  104704
#define OFF_RED   104960
#define SM_TOTAL  105984

__global__ __launch_bounds__(256, 2) void vq_main(const float* __restrict__ z,
                                                  const float* __restrict__ emb,
                                                  float* __restrict__ out,
                                                  int out_size){
  extern __shared__ char smem[];
  const uint32_t sb = smem_u32(smem);
  float* e2s   = (float*)(smem + OFF_E2S);
  float* z2s   = (float*)(smem + OFF_Z2S);
  float* sminv = (float*)(smem + OFF_SMINV);
  int*   smini = (int*)(smem + OFF_SMINI);
  int*   sidx  = (int*)(smem + OFF_SIDX);
  float* red   = (float*)(smem + OFF_RED);

  const int t = threadIdx.x, w = t >> 5, l = t & 31;
  const int wm = (w & 1) * 32;        // 2 m-warps: rows 0-31 / 32-63
  const int g  = w >> 1;              // 4 n-warp groups
  const int wn = g * 32;              // 32 codes per warp within 128-code tile
  const int n0 = blockIdx.x * ROWS_CTA;
  const int b  = n0 >> 12, hw0 = n0 & 4095;
  const float* zb = z + (size_t)b * (C_DIM * HWSZ) + hw0;

  // ---- B cp.async: one stage = [2 s][128 code][32 c] = 16KB ----
  auto issue = [&](int stage){
    const int nt2 = stage >> 3, kc2 = (stage >> 1) & 3, ch2 = stage & 1, buf2 = stage & 1;
    #pragma unroll
    for (int i = 0; i < 4; ++i){
      int id = t + i * 256;          // 0..1023 x 16B
      int s = id >> 9, rem = id & 511;
      int r = rem >> 2, cch = rem & 3;
      const __half* src = g_es + ((size_t)s * K_CODES + nt2 * 128 + r) * C_DIM + kc2 * 64 + ch2 * 32 + cch * 8;
      CPASYNC16(sb + SM_B + buf2 * 16384 + s * 8192 + swz((uint32_t)(r * 64 + cch * 16)), src);
    }
    CPCOMMIT();
  };

  issue(0);
  issue(1);

  // ---- phase 1: all 256 threads split z (4 thr/row); t<64 computes z2 sequentially ----
  {
    const int row = t & 63, q = t >> 6;   // q = kc region
    #pragma unroll
    for (int cg = 0; cg < 8; ++cg){
      uint32_t p0[4], p1[4];
      #pragma unroll
      for (int j2 = 0; j2 < 4; ++j2){
        int c = q * 64 + cg * 8 + j2 * 2;
        float va = __ldg(zb + (size_t)c * HWSZ + row);
        float vb = __ldg(zb + (size_t)(c + 1) * HWSZ + row);
        uint32_t a0, a1, b0, b1;
        split2(va, a0, a1); split2(vb, b0, b1);
        p0[j2] = a0 | (b0 << 16);
        p1[j2] = a1 | (b1 << 16);
      }
      uint32_t ad = swz((uint32_t)(row * 128 + cg * 16));
      STS128(sb + SM_A + q * 16384 + ad,        p0[0], p0[1], p0[2], p0[3]);
      STS128(sb + SM_A + q * 16384 + 8192 + ad, p1[0], p1[1], p1[2], p1[3]);
    }
  }
  for (int i = t; i < 1024; i += 256) e2s[i] = g_e2[i];
  if (t < 64){
    float acc = 0.f;
    #pragma unroll 8
    for (int c = 0; c < 256; ++c){
      float v = __ldg(zb + (size_t)c * HWSZ + t);
      acc = __fadd_rn(acc, __fmul_rn(v, v));
    }
    z2s[t] = acc;
  }
  __syncthreads();

  float z2r[4];
  #pragma unroll
  for (int slot = 0; slot < 4; ++slot){
    int row = wm + (slot >> 1) * 16 + (l >> 2) + (slot & 1) * 8;
    z2r[slot] = z2s[row];
  }

  float acc[2][4][4];
  float minv[4]; int mini[4];
  #pragma unroll
  for (int s2 = 0; s2 < 4; ++s2){ minv[s2] = 3.4028235e38f; mini[s2] = 0; }

  const int pa[3] = {0,0,1}, pb[3] = {0,1,0};

  for (int st = 0; st < 64; ++st){
    const int nt = st >> 3, kc = (st >> 1) & 3, ch = st & 1, buf = st & 1;

    if (st < 63) asm volatile("cp.async.wait_group 1;" ::: "memory");
    else         asm volatile("cp.async.wait_group 0;" ::: "memory");
    __syncthreads();

    if ((st & 7) == 0){
      #pragma unroll
      for (int ma = 0; ma < 2; ++ma)
        #pragma unroll
        for (int na = 0; na < 4; ++na)
          #pragma unroll
          for (int q = 0; q < 4; ++q) acc[ma][na][q] = 0.f;
    }

    const uint32_t Ab = sb + SM_A + (uint32_t)kc * 16384;
    const uint32_t Bb = sb + SM_B + (uint32_t)buf * 16384;
    #pragma unroll
    for (int k16l = 0; k16l < 2; ++k16l){
      const uint32_t kbA = (uint32_t)(ch * 64 + k16l * 32);
      const uint32_t kbB = (uint32_t)(k16l * 32);
      uint32_t af[2][2][4], bf[2][4][2];
      #pragma unroll
      for (int s = 0; s < 2; ++s){
        #pragma unroll
        for (int ma = 0; ma < 2; ++ma){
          uint32_t row = (uint32_t)(wm + ma * 16 + (l & 7) + ((l >> 3) & 1) * 8);
          uint32_t ad = Ab + s * 8192 + swz(row * 128 + kbA + ((l >> 4) << 4));
          LDSM_X4(af[s][ma][0], af[s][ma][1], af[s][ma][2], af[s][ma][3], ad);
        }
        #pragma unroll
        for (int p = 0; p < 2; ++p){
          uint32_t nrow = (uint32_t)(wn + p * 16 + ((l >> 4) << 3) + (l & 7));
          uint32_t bd = Bb + s * 8192 + swz(nrow * 64 + kbB + (((l >> 3) & 1) << 4));
          LDSM_X4(bf[s][2*p][0], bf[s][2*p][1], bf[s][2*p+1][0], bf[s][2*p+1][1], bd);
        }
      }
      #pragma unroll
      for (int p = 0; p < 3; ++p){
        const int sa = pa[p], sbp = pb[p];
        #pragma unroll
        for (int ma = 0; ma < 2; ++ma)
          #pragma unroll
          for (int na = 0; na < 4; ++na)
            MMA16816(acc[ma][na][0], acc[ma][na][1], acc[ma][na][2], acc[ma][na][3],
                     af[sa][ma][0], af[sa][ma][1], af[sa][ma][2], af[sa][ma][3],
                     bf[sbp][na][0], bf[sbp][na][1]);
      }
    }
    __syncthreads();
    if (st + 2 < 64) issue(st + 2);

    if ((st & 7) == 7){
      #pragma unroll
      for (int na = 0; na < 4; ++na){
        #pragma unroll
        for (int c2 = 0; c2 < 2; ++c2){
          int code = nt * 128 + wn + na * 8 + (l & 3) * 2 + c2;
          float e2v = e2s[code];
          #pragma unroll
          for (int ma = 0; ma < 2; ++ma){
            #pragma unroll
            for (int h = 0; h < 2; ++h){
              int slot = ma * 2 + h;
              float dot = acc[ma][na][h * 2 + c2] * EINVSCALE;
              float sd = __fadd_rn(z2r[slot], e2v);
              float dist = __fsub_rn(sd, __fmul_rn(2.0f, dot));
              if (dist < minv[slot]){ minv[slot] = dist; mini[slot] = code; }
            }
          }
        }
      }
    }
  }

  // ---- argmin reduce: 4 lanes per row, then 4 n-warp groups via smem ----
  #pragma unroll
  for (int slot = 0; slot < 4; ++slot){
    #pragma unroll
    for (int m = 1; m <= 2; m <<= 1){
      float ov = __shfl_xor_sync(0xffffffffu, minv[slot], m);
      int   oi = __shfl_xor_sync(0xffffffffu, mini[slot], m);
      if (ov < minv[slot] || (ov == minv[slot] && oi < mini[slot])){ minv[slot] = ov; mini[slot] = oi; }
    }
  }
  if ((l & 3) == 0){
    #pragma unroll
    for (int slot = 0; slot < 4; ++slot){
      int row = wm + (slot >> 1) * 16 + (l >> 2) + (slot & 1) * 8;
      sminv[g * 64 + row] = minv[slot]; smini[g * 64 + row] = mini[slot];
    }
  }
  __syncthreads();
  if (t < 64){
    float bv = sminv[t]; int bi = smini[t];
    #pragma unroll
    for (int gg = 1; gg < 4; ++gg){
      float ov = sminv[gg * 64 + t]; int oi = smini[gg * 64 + t];
      if (ov < bv || (ov == bv && oi < bi)){ bv = ov; bi = oi; }
    }
    sidx[t] = bi;
    if (out_size >= NZQ + N_ROWS) out[NZQ + n0 + t] = (float)bi;
  }
  __syncthreads();

  // ---- fused epilogue: gather zq, straight-through output, loss partial ----
  {
    const int i = t & 63, q = t >> 6;
    const int code = sidx[i];
    const float* erow = emb + (size_t)code * C_DIM;
    float lacc = 0.f;
    const bool wr = (out_size >= NZQ);
    #pragma unroll 4
    for (int c = q; c < 256; c += 4){
      float e  = __ldg(&erow[c]);
      size_t a = (size_t)b * (C_DIM * HWSZ) + hw0 + (size_t)c * HWSZ + i;
      float zp = z[a];
      float d  = __fsub_rn(e, zp);
      if (wr) out[a] = __fadd_rn(zp, d);
      lacc = __fadd_rn(lacc, __fmul_rn(d, d));
    }
    red[t] = lacc;
    __syncthreads();
    for (int s = 128; s > 0; s >>= 1){
      if (t < s) red[t] = __fadd_rn(red[t], red[t + s]);
      __syncthreads();
    }
    if (t == 0) g_partial[blockIdx.x] = red[0];
  }
}

// ---------------- final loss ----------------
__global__ void vq_fin(float* __restrict__ out, int out_size){
  __shared__ double dred[256];
  const int t = threadIdx.x;
  double s = 0.0;
  for (int ii = t; ii < GRID; ii += 256) s += (double)g_partial[ii];
  dred[t] = s;
  __syncthreads();
  for (int k = 128; k > 0; k >>= 1){
    if (t < k) dred[t] += dred[t + k];
    __syncthreads();
  }
  if (t == 0 && out_size >= NZQ + N_ROWS + 1){
    float m1 = (float)(dred[0] / 33554432.0);
    float loss = __fsub_rn(m1, __fmul_rn(0.25f, m1));
    out[NZQ + N_ROWS] = loss;
  }
}

extern "C" void kernel_launch(void* const* d_in, const int* in_sizes, int n_in,
                              void* d_out, int out_size){
  const float* z   = (const float*)d_in[0];
  const float* emb = (const float*)d_in[1];
  float* out = (float*)d_out;
  (void)in_sizes; (void)n_in;

  cudaFuncSetAttribute(vq_main, cudaFuncAttributeMaxDynamicSharedMemorySize, SM_TOTAL);

  prep_e<<<K_CODES, C_DIM>>>(emb);
  vq_main<<<GRID, 256, SM_TOTAL>>>(z, emb, out, out_size);
  vq_fin<<<1, 256>>>(out, out_size);
}